// round 16
// baseline (speedup 1.0000x reference)
#include <cuda_runtime.h>
#include <cuda_bf16.h>
#include <cstdint>

#define TT 512
#define BB 128
#define II 512
#define HH 1024
#define OO 512
#define KK 32
#define G3 (3 * HH)

// ---------------- recurrence config ------------------------------------------
#define NBLK 96
#define NTHR 256
#define NWCOL 32
#define KC 64
#define NCHUNK (HH / KC)    // 16

// recurrence smem (bytes)
#define SM_MBAR 0                           // 3 mbarriers (24 B)
#define SM_A    1024                        // 3 bufs x (hi 16K + lo 16K)
#define A_HL    16384
#define A_BUF   32768
#define SM_W    (SM_A + 3 * A_BUF)          // 99328
#define W_ROWB  2064
#define W_HL    (32 * W_ROWB)               // 66048
#define SMEM_REC (SM_W + 2 * W_HL)          // 231424 (fits 227KB cap)

// ---------------- hmma gemm smem ---------------------------------------------
#define XA_ROWB 80
#define XA_HL   10240
#define XA_BUF  20480
#define XSM_B   (2 * XA_BUF)
#define XSMEM   (XSM_B + 2 * XA_BUF)       // 81920

// ---------------- scratch (static device globals; allocation-free) ----------
__device__ float g_xg[(size_t)BB * TT * G3];          // (B,T,3H) fp32
__device__ float g_ring[(size_t)KK * BB * HH];        // ring [s][b][h] fp32
__device__ float g_hg[(size_t)BB * G3];               // per-step gate GEMM out
__device__ float g_w[KK * HH];                        // flipped lag weights
__device__ __nv_bfloat16 g_hallhi[(size_t)BB * TT * HH];  // linear (decode)
__device__ __nv_bfloat16 g_halllo[(size_t)BB * TT * HH];
// unified pre-swizzled stream: [t][chunk16][hi 16KB | lo 16KB] (32KB blocks)
__device__ __nv_bfloat16 g_s[(size_t)TT * BB * HH * 2];
__device__ __nv_bfloat16 g_xhi[(size_t)BB * TT * II];
__device__ __nv_bfloat16 g_xlo[(size_t)BB * TT * II];
__device__ __nv_bfloat16 g_wihhi[(size_t)G3 * II];
__device__ __nv_bfloat16 g_wihlo[(size_t)G3 * II];
__device__ __nv_bfloat16 g_wohi[(size_t)OO * HH];
__device__ __nv_bfloat16 g_wolo[(size_t)OO * HH];
__device__ unsigned int g_barrier;

// ---------------- PTX helpers ------------------------------------------------
__device__ __forceinline__ uint32_t smem_u32(const void* p) {
    uint32_t a;
    asm("{ .reg .u64 t; cvta.to.shared.u64 t, %1; cvt.u32.u64 %0, t; }" : "=r"(a) : "l"(p));
    return a;
}
__device__ __forceinline__ void cpa16(uint32_t dst, const void* src) {
    asm volatile("cp.async.cg.shared.global [%0], [%1], 16;" :: "r"(dst), "l"(src));
}
__device__ __forceinline__ void cpa_commit() { asm volatile("cp.async.commit_group;"); }
template <int N> __device__ __forceinline__ void cpa_wait() {
    asm volatile("cp.async.wait_group %0;" :: "n"(N));
}
__device__ __forceinline__ void bulk_cp(uint32_t dst, const void* src, uint32_t bytes,
                                        uint32_t mbar) {
    asm volatile(
        "cp.async.bulk.shared::cta.global.mbarrier::complete_tx::bytes [%0], [%1], %2, [%3];"
        :: "r"(dst), "l"(src), "r"(bytes), "r"(mbar) : "memory");
}
__device__ __forceinline__ void mbar_init(uint32_t mbar, uint32_t cnt) {
    asm volatile("mbarrier.init.shared.b64 [%0], %1;" :: "r"(mbar), "r"(cnt) : "memory");
}
__device__ __forceinline__ void mbar_expect_tx(uint32_t mbar, uint32_t tx) {
    asm volatile("mbarrier.arrive.expect_tx.shared.b64 _, [%0], %1;"
                 :: "r"(mbar), "r"(tx) : "memory");
}
__device__ __forceinline__ void mbar_wait(uint32_t mbar, uint32_t parity) {
    asm volatile(
        "{\n\t.reg .pred P1;\n\t"
        "WL_%=:\n\t"
        "mbarrier.try_wait.parity.acquire.cta.shared::cta.b64 P1, [%0], %1, 0x989680;\n\t"
        "@P1 bra.uni WD_%=;\n\t"
        "bra.uni WL_%=;\n\t"
        "WD_%=:\n\t}"
        :: "r"(mbar), "r"(parity) : "memory");
}
__device__ __forceinline__ void ldsm_x4(uint32_t* r, uint32_t addr) {
    asm volatile("ldmatrix.sync.aligned.m8n8.x4.shared.b16 {%0,%1,%2,%3}, [%4];"
                 : "=r"(r[0]), "=r"(r[1]), "=r"(r[2]), "=r"(r[3]) : "r"(addr));
}
__device__ __forceinline__ void mma_bf16(float* c, const uint32_t* a, uint32_t b0, uint32_t b1) {
    asm volatile(
        "mma.sync.aligned.m16n8k16.row.col.f32.bf16.bf16.f32 "
        "{%0,%1,%2,%3}, {%4,%5,%6,%7}, {%8,%9}, {%0,%1,%2,%3};"
        : "+f"(c[0]), "+f"(c[1]), "+f"(c[2]), "+f"(c[3])
        : "r"(a[0]), "r"(a[1]), "r"(a[2]), "r"(a[3]), "r"(b0), "r"(b1));
}

// ---------------- prep kernels -----------------------------------------------
__global__ void compute_w_kernel(const float* __restrict__ mem_para) {
    int h = blockIdx.x * blockDim.x + threadIdx.x;
    if (h >= HH) return;
    float d = 0.5f / (1.0f + expf(-mem_para[h]));
    float cum = 1.0f;
    for (int k = 0; k < KK; k++) {
        cum *= ((float)k - d) / ((float)k + 1.0f);
        g_w[(KK - 1 - k) * HH + h] = cum;
    }
}

__global__ void init_kernel() {
    size_t stride = (size_t)gridDim.x * blockDim.x;
    size_t i0 = (size_t)blockIdx.x * blockDim.x + threadIdx.x;
    for (size_t i = i0; i < (size_t)KK * BB * HH; i += stride) g_ring[i] = 0.0f;
    if (blockIdx.x == 0 && threadIdx.x == 0) g_barrier = 0u;
}

__global__ void convert_kernel(const float* __restrict__ x,
                               const float* __restrict__ wih,
                               const float* __restrict__ wout) {
    size_t stride = (size_t)gridDim.x * blockDim.x;
    size_t i0 = (size_t)blockIdx.x * blockDim.x + threadIdx.x;
    for (size_t i = i0; i < (size_t)BB * TT * II; i += stride) {
        float v = x[i];
        __nv_bfloat16 hi = __float2bfloat16(v);
        g_xhi[i] = hi;
        g_xlo[i] = __float2bfloat16(v - __bfloat162float(hi));
    }
    for (size_t i = i0; i < (size_t)G3 * II; i += stride) {
        float v = wih[i];
        __nv_bfloat16 hi = __float2bfloat16(v);
        g_wihhi[i] = hi;
        g_wihlo[i] = __float2bfloat16(v - __bfloat162float(hi));
    }
    for (size_t i = i0; i < (size_t)OO * HH; i += stride) {
        float v = wout[i];
        __nv_bfloat16 hi = __float2bfloat16(v);
        g_wohi[i] = hi;
        g_wolo[i] = __float2bfloat16(v - __bfloat162float(hi));
    }
}

__global__ void copy_kernel(const float* __restrict__ src, float* __restrict__ dst, size_t n) {
    size_t stride = (size_t)gridDim.x * blockDim.x;
    for (size_t i = (size_t)blockIdx.x * blockDim.x + threadIdx.x; i < n; i += stride)
        dst[i] = src[i];
}

// ---------------- generic HMMA GEMM: C = A @ B^T (+bias, opt tanh) -----------
template <int KD, int ND, int EPI>
__global__ void __launch_bounds__(256, 1)
gemm_hmma(const __nv_bfloat16* __restrict__ Ahi, const __nv_bfloat16* __restrict__ Alo,
          const __nv_bfloat16* __restrict__ Bhi, const __nv_bfloat16* __restrict__ Blo,
          float* __restrict__ C, const float* __restrict__ bias) {
    extern __shared__ char smx[];
    const uint32_t sbx = smem_u32(smx);
    const int tid = threadIdx.x;
    const int wid = tid >> 5;
    const int lane = tid & 31;
    const int wm = wid & 3;
    const int wn = wid >> 2;
    const int brow0 = blockIdx.y * 128;
    const int bcol0 = blockIdx.x * 128;

    const char* ahi = (const char*)Ahi;
    const char* alo = (const char*)Alo;
    const char* bhi = (const char*)Bhi;
    const char* blo = (const char*)Blo;

    float acc[2][8][4];
#pragma unroll
    for (int i = 0; i < 2; i++)
#pragma unroll
        for (int j = 0; j < 8; j++)
#pragma unroll
            for (int q = 0; q < 4; q++) acc[i][j][q] = 0.0f;

    auto fill = [&](int c, int buf) {
        uint32_t ab = sbx + buf * XA_BUF;
        uint32_t bb = sbx + XSM_B + buf * XA_BUF;
#pragma unroll
        for (int j = 0; j < 4; j++) {
            int g = tid + j * 256;
            int half = g >> 9, w = g & 511;
            int row = w >> 2, u = w & 3;
            cpa16(ab + half * XA_HL + row * XA_ROWB + u * 16,
                  (half ? alo : ahi) + ((size_t)(brow0 + row) * KD + c * 32 + u * 8) * 2);
        }
#pragma unroll
        for (int j = 0; j < 4; j++) {
            int g = tid + j * 256;
            int half = g >> 9, w = g & 511;
            int row = w >> 2, u = w & 3;
            cpa16(bb + half * XA_HL + row * XA_ROWB + u * 16,
                  (half ? blo : bhi) + ((size_t)(bcol0 + row) * KD + c * 32 + u * 8) * 2);
        }
    };

    fill(0, 0);
    cpa_commit();

    const int arow = (lane & 7) + ((lane >> 3) & 1) * 8;
    const uint32_t acol16 = (uint32_t)(lane >> 4) * 16;   // BYTES
    const int brow = lane & 7;
    const uint32_t bquad16 = (uint32_t)(lane >> 3) * 16;  // BYTES

    constexpr int NC = KD / 32;
    for (int c = 0; c < NC; c++) {
        cpa_wait<0>();
        __syncthreads();
        if (c + 1 < NC) { fill(c + 1, (c + 1) & 1); cpa_commit(); }

        uint32_t ab = sbx + (c & 1) * XA_BUF;
        uint32_t bb = sbx + XSM_B + (c & 1) * XA_BUF;

        uint32_t bh[8][4], bl[8][4];
#pragma unroll
        for (int j = 0; j < 8; j++) {
            uint32_t ba = bb + (uint32_t)(wn * 64 + j * 8 + brow) * XA_ROWB + bquad16;
            ldsm_x4(bh[j], ba);
            ldsm_x4(bl[j], ba + XA_HL);
        }
#pragma unroll
        for (int sh = 0; sh < 2; sh++) {
            uint32_t ah[2][4], al[2][4];
#pragma unroll
            for (int i = 0; i < 2; i++) {
                uint32_t aa = ab + (uint32_t)(wm * 32 + i * 16 + arow) * XA_ROWB +
                              sh * 32 + acol16;
                ldsm_x4(ah[i], aa);
                ldsm_x4(al[i], aa + XA_HL);
            }
#pragma unroll
            for (int i = 0; i < 2; i++)
#pragma unroll
                for (int j = 0; j < 8; j++) {
                    mma_bf16(acc[i][j], ah[i], bh[j][sh * 2], bh[j][sh * 2 + 1]);
                    mma_bf16(acc[i][j], ah[i], bl[j][sh * 2], bl[j][sh * 2 + 1]);
                    mma_bf16(acc[i][j], al[i], bh[j][sh * 2], bh[j][sh * 2 + 1]);
                }
        }
        __syncthreads();
    }

    const int qrow = lane >> 2;
    const int qcol = (lane & 3) * 2;
#pragma unroll
    for (int i = 0; i < 2; i++) {
        int m0 = brow0 + wm * 32 + i * 16 + qrow;
#pragma unroll
        for (int j = 0; j < 8; j++) {
            int n0 = bcol0 + wn * 64 + j * 8 + qcol;
            float bi0 = bias[n0], bi1 = bias[n0 + 1];
            float v00 = acc[i][j][0] + bi0, v01 = acc[i][j][1] + bi1;
            float v10 = acc[i][j][2] + bi0, v11 = acc[i][j][3] + bi1;
            if (EPI == 1) {
                v00 = tanhf(v00); v01 = tanhf(v01);
                v10 = tanhf(v10); v11 = tanhf(v11);
            }
            *(float2*)(C + (size_t)m0 * ND + n0) = make_float2(v00, v01);
            *(float2*)(C + (size_t)(m0 + 8) * ND + n0) = make_float2(v10, v11);
        }
    }
}

// ---------------- grid-wide barrier (tight spin) -------------------------------
__device__ __forceinline__ void grid_bar() {
    __syncthreads();
    if (threadIdx.x == 0) {
        __threadfence();
        unsigned int arr = atomicAdd(&g_barrier, 1u);
        unsigned int target = arr - (arr % NBLK) + NBLK;
        unsigned int spins = 0;
        while (*(volatile unsigned int*)&g_barrier < target) {
            if (++spins > 2048u) __nanosleep(64);
        }
    }
    __syncthreads();
}

// ---------------- persistent HMMA recurrence ----------------------------------
// 96 blocks x 256 threads. A chunks: single 32KB cp.async.bulk each, 3-buffer
// pipeline with depth-2 prefetch; W hi/lo resident in smem.
__global__ void __launch_bounds__(NTHR, 1)
recurrence_kernel(const float* __restrict__ W_hh, const float* __restrict__ b_hh) {
    extern __shared__ char smem[];
    const uint32_t sb = smem_u32(smem);
    const int tid = threadIdx.x;
    const int wid = tid >> 5;
    const int lane = tid & 31;
    const int blk = blockIdx.x;
    const int col0 = blk * NWCOL;
    const int wm = wid & 3;
    const int wn = wid >> 2;

    if (tid == 0) {
        mbar_init(sb + SM_MBAR, 1);
        mbar_init(sb + SM_MBAR + 8, 1);
        mbar_init(sb + SM_MBAR + 16, 1);
    }

    // W slice: fp32 -> bf16 hi/lo, padded row-major (n,k), smem-resident
    for (int idx = tid; idx < NWCOL * HH; idx += NTHR) {
        int r = idx >> 10;
        int k = idx & 1023;
        float w = W_hh[(size_t)(col0 + r) * HH + k];
        __nv_bfloat16 hi = __float2bfloat16(w);
        __nv_bfloat16 lo = __float2bfloat16(w - __bfloat162float(hi));
        *(__nv_bfloat16*)(smem + SM_W + r * W_ROWB + k * 2) = hi;
        *(__nv_bfloat16*)(smem + SM_W + W_HL + r * W_ROWB + k * 2) = lo;
    }
    __syncthreads();

    // A-fragment lane constants: row r = wm*32 + i*16 + arow; SW128 layout
    const int arow = (lane & 7) + ((lane >> 3) & 1) * 8;
    const uint32_t acol16 = (uint32_t)(lane >> 4) * 16;   // BYTES
    uint32_t rbase[2], rxor[2];
#pragma unroll
    for (int i = 0; i < 2; i++) {
        int r = wm * 32 + i * 16 + arow;
        rbase[i] = ((uint32_t)(r >> 3) << 10) + ((uint32_t)(r & 7) << 7);
        rxor[i] = (uint32_t)(r & 7) << 4;
    }
    // B-fragment x4 lane mapping
    const int brow4 = wn * 16 + ((lane >> 4) & 1) * 8 + (lane & 7);
    const int bcol4 = ((lane >> 3) & 1) * 8;
    const uint32_t wb_hi = sb + SM_W + (uint32_t)brow4 * W_ROWB + (uint32_t)bcol4 * 2;
    const uint32_t wb_lo = wb_hi + W_HL;

    const char* sstream = (const char*)g_s;

    // phase-B loop invariants: h4 = 4*tid
    const int h4 = (tid & 255) << 2;
    const float4 bz  = *(const float4*)(b_hh + h4);
    const float4 brr = *(const float4*)(b_hh + HH + h4);
    const float4 bnn = *(const float4*)(b_hh + 2 * HH + h4);

    uint32_t parity[3] = {0u, 0u, 0u};

    for (int t = 0; t < TT; t++) {
        float a0[2][2][4], a1[2][2][4], a2[2][2][4];
#pragma unroll
        for (int i = 0; i < 2; i++)
#pragma unroll
            for (int j = 0; j < 2; j++)
#pragma unroll
                for (int q = 0; q < 4; q++) {
                    a0[i][j][q] = 0.0f; a1[i][j][q] = 0.0f; a2[i][j][q] = 0.0f;
                }

        if (t > 0) {
            const size_t tbase = (size_t)(t - 1) * NCHUNK * A_BUF;
            // preamble: prefetch chunks 0,1 into bufs 0,1
            if (tid == 0) {
#pragma unroll
                for (int p = 0; p < 2; p++) {
                    uint32_t mb = sb + SM_MBAR + p * 8;
                    mbar_expect_tx(mb, A_BUF);
                    bulk_cp(sb + SM_A + p * A_BUF, sstream + tbase + (size_t)p * A_BUF,
                            A_BUF, mb);
                }
            }

            for (int c = 0; c < NCHUNK; c++) {
                int buf = c % 3;
                if (c + 2 < NCHUNK && tid == 0) {
                    int nbuf = (c + 2) % 3;
                    uint32_t mb = sb + SM_MBAR + nbuf * 8;
                    mbar_expect_tx(mb, A_BUF);
                    bulk_cp(sb + SM_A + nbuf * A_BUF,
                            sstream + tbase + (size_t)(c + 2) * A_BUF, A_BUF, mb);
                }
                mbar_wait(sb + SM_MBAR + buf * 8, parity[buf]);
                parity[buf] ^= 1;

                uint32_t abuf = sb + SM_A + buf * A_BUF;
#pragma unroll
                for (int s = 0; s < 4; s++) {
                    uint32_t bytecol = (uint32_t)s * 32 + acol16;
                    uint32_t kgb = (uint32_t)(c * KC + s * 16) * 2;
                    uint32_t ah[2][4], al[2][4];
#pragma unroll
                    for (int i = 0; i < 2; i++) {
                        uint32_t aoff = rbase[i] + (bytecol ^ rxor[i]);
                        ldsm_x4(ah[i], abuf + aoff);
                        ldsm_x4(al[i], abuf + A_HL + aoff);
                    }
                    uint32_t bh[4], bl[4];
                    ldsm_x4(bh, wb_hi + kgb);
                    ldsm_x4(bl, wb_lo + kgb);
#pragma unroll
                    for (int i = 0; i < 2; i++) {
                        mma_bf16(a0[i][0], ah[i], bh[0], bh[1]);
                        mma_bf16(a0[i][1], ah[i], bh[2], bh[3]);
                    }
#pragma unroll
                    for (int i = 0; i < 2; i++) {
                        mma_bf16(a1[i][0], ah[i], bl[0], bl[1]);
                        mma_bf16(a1[i][1], ah[i], bl[2], bl[3]);
                    }
#pragma unroll
                    for (int i = 0; i < 2; i++) {
                        mma_bf16(a2[i][0], al[i], bh[0], bh[1]);
                        mma_bf16(a2[i][1], al[i], bh[2], bh[3]);
                    }
                }
                __syncthreads();   // all warps done reading buf before reuse
            }
        }

        // epilogue: combine terms -> g_hg
        {
            int qrow = lane >> 2;
            int qcol = (lane & 3) * 2;
#pragma unroll
            for (int i = 0; i < 2; i++) {
                int m0 = wm * 32 + i * 16 + qrow;
#pragma unroll
                for (int j = 0; j < 2; j++) {
                    int n0 = col0 + wn * 16 + j * 8 + qcol;
                    float v0 = a0[i][j][0] + a1[i][j][0] + a2[i][j][0];
                    float v1 = a0[i][j][1] + a1[i][j][1] + a2[i][j][1];
                    float v2 = a0[i][j][2] + a1[i][j][2] + a2[i][j][2];
                    float v3 = a0[i][j][3] + a1[i][j][3] + a2[i][j][3];
                    *(float2*)(g_hg + (size_t)m0 * G3 + n0) = make_float2(v0, v1);
                    *(float2*)(g_hg + (size_t)(m0 + 8) * G3 + n0) = make_float2(v2, v3);
                }
            }
        }

        grid_bar();  // hg complete everywhere

        // ---- phase B: gates + fractional memory, float4-vectorized ----------
        const int ng = (BB * HH) / 4;
        for (int g = blk * NTHR + tid; g < ng; g += NBLK * NTHR) {
            int b = g >> 8;
            int hc = g & 255;
            const float4* xrow = (const float4*)(g_xg + ((size_t)b * TT + t) * G3);
            float4 xz = xrow[hc];
            float4 xr = xrow[256 + hc];
            float4 xn = xrow[512 + hc];
            const float4* hrow = (const float4*)(g_hg + (size_t)b * G3);
            float4 hz4 = __ldcg(hrow + hc);
            float4 hr4 = __ldcg(hrow + 256 + hc);
            float4 hn4 = __ldcg(hrow + 512 + hc);

            float m0 = 0.f, m1 = 0.f, m2 = 0.f, m3 = 0.f;
#pragma unroll
            for (int k = 0; k < KK; k++) {
                int s = (t + k) & (KK - 1);
                float4 wv = *(const float4*)(g_w + (size_t)k * HH + h4);
                float4 rv = __ldcg((const float4*)(g_ring +
                                   ((size_t)s * BB + b) * HH + h4));
                m0 += wv.x * rv.x; m1 += wv.y * rv.y;
                m2 += wv.z * rv.z; m3 += wv.w * rv.w;
            }

            float XZ[4] = {xz.x, xz.y, xz.z, xz.w};
            float XR[4] = {xr.x, xr.y, xr.z, xr.w};
            float XN[4] = {xn.x, xn.y, xn.z, xn.w};
            float HZ[4] = {hz4.x + bz.x, hz4.y + bz.y, hz4.z + bz.z, hz4.w + bz.w};
            float HR[4] = {hr4.x + brr.x, hr4.y + brr.y, hr4.z + brr.z, hr4.w + brr.w};
            float HN[4] = {hn4.x + bnn.x, hn4.y + bnn.y, hn4.z + bnn.z, hn4.w + bnn.w};
            float MM[4] = {m0, m1, m2, m3};
            float hnew[4];
#pragma unroll
            for (int q = 0; q < 4; q++) {
                float z = 1.0f / (1.0f + expf(-(XZ[q] + HZ[q])));
                float r = 1.0f / (1.0f + expf(-(XR[q] + HR[q])));
                float n = tanhf(XN[q] + r * HN[q]);
                hnew[q] = z * n - MM[q];
            }

            *(float4*)(g_ring + ((size_t)(t & (KK - 1)) * BB + b) * HH + h4) =
                make_float4(hnew[0], hnew[1], hnew[2], hnew[3]);

            __nv_bfloat16 hb[4], lb[4];
#pragma unroll
            for (int q = 0; q < 4; q++) {
                hb[q] = __float2bfloat16(hnew[q]);
                lb[q] = __float2bfloat16(hnew[q] - __bfloat162float(hb[q]));
            }
            uint2 hpack, lpack;
            hpack.x = ((uint32_t)*(unsigned short*)&hb[1] << 16) | *(unsigned short*)&hb[0];
            hpack.y = ((uint32_t)*(unsigned short*)&hb[3] << 16) | *(unsigned short*)&hb[2];
            lpack.x = ((uint32_t)*(unsigned short*)&lb[1] << 16) | *(unsigned short*)&lb[0];
            lpack.y = ((uint32_t)*(unsigned short*)&lb[3] << 16) | *(unsigned short*)&lb[2];

            // linear copy (decode)
            size_t hidx = ((size_t)b * TT + t) * HH + h4;
            *(uint2*)(g_hallhi + hidx) = hpack;
            *(uint2*)(g_halllo + hidx) = lpack;

            // pre-swizzled unified stream: [t][chunk][hi 16K | lo 16K]
            int cch = h4 >> 6;
            uint32_t within = ((uint32_t)(b & 7) << 7) +
                              ((((uint32_t)(h4 & 63)) << 1) ^ (((uint32_t)(b & 7)) << 4));
            size_t soff = ((size_t)t * NCHUNK + cch) * A_BUF +
                          ((size_t)(b >> 3) << 10) + within;
            *(uint2*)((char*)g_s + soff) = hpack;
            *(uint2*)((char*)g_s + soff + A_HL) = lpack;
        }

        grid_bar();  // h_new visible everywhere before next step's A stream
    }
}

// ---------------- launch ------------------------------------------------------
extern "C" void kernel_launch(void* const* d_in, const int* in_sizes, int n_in,
                              void* d_out, int out_size) {
    const float* input_seq = (const float*)d_in[0];
    const float* mem_para  = (const float*)d_in[1];
    const float* W_ih      = (const float*)d_in[2];
    const float* W_hh      = (const float*)d_in[3];
    const float* b_ih      = (const float*)d_in[4];
    const float* b_hh      = (const float*)d_in[5];
    const float* W_out     = (const float*)d_in[6];
    const float* b_out     = (const float*)d_in[7];
    float* out = (float*)d_out;

    cudaFuncSetAttribute(recurrence_kernel,
                         cudaFuncAttributeMaxDynamicSharedMemorySize, SMEM_REC);
    cudaFuncSetAttribute(gemm_hmma<II, G3, 0>,
                         cudaFuncAttributeMaxDynamicSharedMemorySize, XSMEM);
    cudaFuncSetAttribute(gemm_hmma<HH, OO, 1>,
                         cudaFuncAttributeMaxDynamicSharedMemorySize, XSMEM);

    float *xg, *ring;
    __nv_bfloat16 *xhi, *xlo, *wihhi, *wihlo, *hallhi, *halllo, *wohi, *wolo;
    cudaGetSymbolAddress((void**)&xg, g_xg);
    cudaGetSymbolAddress((void**)&ring, g_ring);
    cudaGetSymbolAddress((void**)&xhi, g_xhi);
    cudaGetSymbolAddress((void**)&xlo, g_xlo);
    cudaGetSymbolAddress((void**)&wihhi, g_wihhi);
    cudaGetSymbolAddress((void**)&wihlo, g_wihlo);
    cudaGetSymbolAddress((void**)&hallhi, g_hallhi);
    cudaGetSymbolAddress((void**)&halllo, g_halllo);
    cudaGetSymbolAddress((void**)&wohi, g_wohi);
    cudaGetSymbolAddress((void**)&wolo, g_wolo);

    compute_w_kernel<<<1, 1024>>>(mem_para);
    init_kernel<<<1024, 256>>>();
    convert_kernel<<<2048, 256>>>(input_seq, W_ih, W_out);

    {   // xg = input_seq @ W_ih^T + b_ih  (HMMA 3-term bf16)
        dim3 grid(G3 / 128, (BB * TT) / 128);
        gemm_hmma<II, G3, 0><<<grid, 256, XSMEM>>>(xhi, xlo, wihhi, wihlo, xg, b_ih);
    }

    recurrence_kernel<<<NBLK, NTHR, SMEM_REC>>>(W_hh, b_hh);

    {   // decode: out[b*TT+t][o] = tanh(Hall @ W_out^T + b_out)  (HMMA)
        dim3 grid(OO / 128, (BB * TT) / 128);
        gemm_hmma<HH, OO, 1><<<grid, 256, XSMEM>>>(hallhi, halllo, wohi, wolo, out, b_out);
    }

    size_t dec_elems = (size_t)BB * TT * OO;
    size_t hbuf_elems = (size_t)KK * BB * HH;
    if ((size_t)out_size >= dec_elems + hbuf_elems) {
        copy_kernel<<<1024, 256>>>(ring, out + dec_elems, hbuf_elems);
    }
}

// round 17
// speedup vs baseline: 1.0626x; 1.0626x over previous
#include <cuda_runtime.h>
#include <cuda_bf16.h>
#include <cstdint>

#define TT 512
#define BB 128
#define II 512
#define HH 1024
#define OO 512
#define KK 32
#define G3 (3 * HH)

// ---------------- recurrence config ------------------------------------------
#define NBLK 96
#define NTHR 256
#define NWCOL 32
#define KC 64
#define NCHUNK (HH / KC)    // 16

// recurrence smem (bytes) -- R15-proven footprint (L1D keeps ~29KB)
#define SM_MBAR 0                           // 2 mbarriers (16 B)
#define SM_A    1024                        // 2 bufs x (hi 16K | lo 16K)
#define A_HL    16384
#define A_BUF   32768
#define SM_W    (SM_A + 2 * A_BUF)          // 66560
#define W_ROWB  2064
#define W_HL    (32 * W_ROWB)               // 66048
#define SMEM_REC (SM_W + 2 * W_HL)          // 198656

// ---------------- hmma gemm smem ---------------------------------------------
#define XA_ROWB 80
#define XA_HL   10240
#define XA_BUF  20480
#define XSM_B   (2 * XA_BUF)
#define XSMEM   (XSM_B + 2 * XA_BUF)       // 81920

// ---------------- scratch (static device globals; allocation-free) ----------
__device__ float g_xg[(size_t)BB * TT * G3];          // (B,T,3H) fp32
__device__ float g_ring[(size_t)KK * BB * HH];        // ring [s][b][h] fp32
__device__ float g_hg[(size_t)BB * G3];               // per-step gate GEMM out
__device__ float g_w[KK * HH];                        // flipped lag weights
__device__ __nv_bfloat16 g_hallhi[(size_t)BB * TT * HH];  // linear (decode)
__device__ __nv_bfloat16 g_halllo[(size_t)BB * TT * HH];
// unified pre-swizzled stream: [t][chunk16][hi 16KB | lo 16KB] (32KB blocks)
__device__ __nv_bfloat16 g_s[(size_t)TT * BB * HH * 2];
__device__ __nv_bfloat16 g_xhi[(size_t)BB * TT * II];
__device__ __nv_bfloat16 g_xlo[(size_t)BB * TT * II];
__device__ __nv_bfloat16 g_wihhi[(size_t)G3 * II];
__device__ __nv_bfloat16 g_wihlo[(size_t)G3 * II];
__device__ __nv_bfloat16 g_wohi[(size_t)OO * HH];
__device__ __nv_bfloat16 g_wolo[(size_t)OO * HH];
__device__ unsigned int g_barrier;

// ---------------- PTX helpers ------------------------------------------------
__device__ __forceinline__ uint32_t smem_u32(const void* p) {
    uint32_t a;
    asm("{ .reg .u64 t; cvta.to.shared.u64 t, %1; cvt.u32.u64 %0, t; }" : "=r"(a) : "l"(p));
    return a;
}
__device__ __forceinline__ void cpa16(uint32_t dst, const void* src) {
    asm volatile("cp.async.cg.shared.global [%0], [%1], 16;" :: "r"(dst), "l"(src));
}
__device__ __forceinline__ void cpa_commit() { asm volatile("cp.async.commit_group;"); }
template <int N> __device__ __forceinline__ void cpa_wait() {
    asm volatile("cp.async.wait_group %0;" :: "n"(N));
}
__device__ __forceinline__ void bulk_cp(uint32_t dst, const void* src, uint32_t bytes,
                                        uint32_t mbar) {
    asm volatile(
        "cp.async.bulk.shared::cta.global.mbarrier::complete_tx::bytes [%0], [%1], %2, [%3];"
        :: "r"(dst), "l"(src), "r"(bytes), "r"(mbar) : "memory");
}
__device__ __forceinline__ void mbar_init(uint32_t mbar, uint32_t cnt) {
    asm volatile("mbarrier.init.shared.b64 [%0], %1;" :: "r"(mbar), "r"(cnt) : "memory");
}
__device__ __forceinline__ void mbar_expect_tx(uint32_t mbar, uint32_t tx) {
    asm volatile("mbarrier.arrive.expect_tx.shared.b64 _, [%0], %1;"
                 :: "r"(mbar), "r"(tx) : "memory");
}
__device__ __forceinline__ void mbar_wait(uint32_t mbar, uint32_t parity) {
    asm volatile(
        "{\n\t.reg .pred P1;\n\t"
        "WL_%=:\n\t"
        "mbarrier.try_wait.parity.acquire.cta.shared::cta.b64 P1, [%0], %1, 0x989680;\n\t"
        "@P1 bra.uni WD_%=;\n\t"
        "bra.uni WL_%=;\n\t"
        "WD_%=:\n\t}"
        :: "r"(mbar), "r"(parity) : "memory");
}
__device__ __forceinline__ void ldsm_x4(uint32_t* r, uint32_t addr) {
    asm volatile("ldmatrix.sync.aligned.m8n8.x4.shared.b16 {%0,%1,%2,%3}, [%4];"
                 : "=r"(r[0]), "=r"(r[1]), "=r"(r[2]), "=r"(r[3]) : "r"(addr));
}
__device__ __forceinline__ void mma_bf16(float* c, const uint32_t* a, uint32_t b0, uint32_t b1) {
    asm volatile(
        "mma.sync.aligned.m16n8k16.row.col.f32.bf16.bf16.f32 "
        "{%0,%1,%2,%3}, {%4,%5,%6,%7}, {%8,%9}, {%0,%1,%2,%3};"
        : "+f"(c[0]), "+f"(c[1]), "+f"(c[2]), "+f"(c[3])
        : "r"(a[0]), "r"(a[1]), "r"(a[2]), "r"(a[3]), "r"(b0), "r"(b1));
}

// ---------------- prep kernels -----------------------------------------------
__global__ void compute_w_kernel(const float* __restrict__ mem_para) {
    int h = blockIdx.x * blockDim.x + threadIdx.x;
    if (h >= HH) return;
    float d = 0.5f / (1.0f + expf(-mem_para[h]));
    float cum = 1.0f;
    for (int k = 0; k < KK; k++) {
        cum *= ((float)k - d) / ((float)k + 1.0f);
        g_w[(KK - 1 - k) * HH + h] = cum;
    }
}

__global__ void init_kernel() {
    size_t stride = (size_t)gridDim.x * blockDim.x;
    size_t i0 = (size_t)blockIdx.x * blockDim.x + threadIdx.x;
    for (size_t i = i0; i < (size_t)KK * BB * HH; i += stride) g_ring[i] = 0.0f;
    if (blockIdx.x == 0 && threadIdx.x == 0) g_barrier = 0u;
}

__global__ void convert_kernel(const float* __restrict__ x,
                               const float* __restrict__ wih,
                               const float* __restrict__ wout) {
    size_t stride = (size_t)gridDim.x * blockDim.x;
    size_t i0 = (size_t)blockIdx.x * blockDim.x + threadIdx.x;
    for (size_t i = i0; i < (size_t)BB * TT * II; i += stride) {
        float v = x[i];
        __nv_bfloat16 hi = __float2bfloat16(v);
        g_xhi[i] = hi;
        g_xlo[i] = __float2bfloat16(v - __bfloat162float(hi));
    }
    for (size_t i = i0; i < (size_t)G3 * II; i += stride) {
        float v = wih[i];
        __nv_bfloat16 hi = __float2bfloat16(v);
        g_wihhi[i] = hi;
        g_wihlo[i] = __float2bfloat16(v - __bfloat162float(hi));
    }
    for (size_t i = i0; i < (size_t)OO * HH; i += stride) {
        float v = wout[i];
        __nv_bfloat16 hi = __float2bfloat16(v);
        g_wohi[i] = hi;
        g_wolo[i] = __float2bfloat16(v - __bfloat162float(hi));
    }
}

__global__ void copy_kernel(const float* __restrict__ src, float* __restrict__ dst, size_t n) {
    size_t stride = (size_t)gridDim.x * blockDim.x;
    for (size_t i = (size_t)blockIdx.x * blockDim.x + threadIdx.x; i < n; i += stride)
        dst[i] = src[i];
}

// ---------------- generic HMMA GEMM: C = A @ B^T (+bias, opt tanh) -----------
template <int KD, int ND, int EPI>
__global__ void __launch_bounds__(256, 1)
gemm_hmma(const __nv_bfloat16* __restrict__ Ahi, const __nv_bfloat16* __restrict__ Alo,
          const __nv_bfloat16* __restrict__ Bhi, const __nv_bfloat16* __restrict__ Blo,
          float* __restrict__ C, const float* __restrict__ bias) {
    extern __shared__ char smx[];
    const uint32_t sbx = smem_u32(smx);
    const int tid = threadIdx.x;
    const int wid = tid >> 5;
    const int lane = tid & 31;
    const int wm = wid & 3;
    const int wn = wid >> 2;
    const int brow0 = blockIdx.y * 128;
    const int bcol0 = blockIdx.x * 128;

    const char* ahi = (const char*)Ahi;
    const char* alo = (const char*)Alo;
    const char* bhi = (const char*)Bhi;
    const char* blo = (const char*)Blo;

    float acc[2][8][4];
#pragma unroll
    for (int i = 0; i < 2; i++)
#pragma unroll
        for (int j = 0; j < 8; j++)
#pragma unroll
            for (int q = 0; q < 4; q++) acc[i][j][q] = 0.0f;

    auto fill = [&](int c, int buf) {
        uint32_t ab = sbx + buf * XA_BUF;
        uint32_t bb = sbx + XSM_B + buf * XA_BUF;
#pragma unroll
        for (int j = 0; j < 4; j++) {
            int g = tid + j * 256;
            int half = g >> 9, w = g & 511;
            int row = w >> 2, u = w & 3;
            cpa16(ab + half * XA_HL + row * XA_ROWB + u * 16,
                  (half ? alo : ahi) + ((size_t)(brow0 + row) * KD + c * 32 + u * 8) * 2);
        }
#pragma unroll
        for (int j = 0; j < 4; j++) {
            int g = tid + j * 256;
            int half = g >> 9, w = g & 511;
            int row = w >> 2, u = w & 3;
            cpa16(bb + half * XA_HL + row * XA_ROWB + u * 16,
                  (half ? blo : bhi) + ((size_t)(bcol0 + row) * KD + c * 32 + u * 8) * 2);
        }
    };

    fill(0, 0);
    cpa_commit();

    const int arow = (lane & 7) + ((lane >> 3) & 1) * 8;
    const uint32_t acol16 = (uint32_t)(lane >> 4) * 16;   // BYTES
    const int brow = lane & 7;
    const uint32_t bquad16 = (uint32_t)(lane >> 3) * 16;  // BYTES

    constexpr int NC = KD / 32;
    for (int c = 0; c < NC; c++) {
        cpa_wait<0>();
        __syncthreads();
        if (c + 1 < NC) { fill(c + 1, (c + 1) & 1); cpa_commit(); }

        uint32_t ab = sbx + (c & 1) * XA_BUF;
        uint32_t bb = sbx + XSM_B + (c & 1) * XA_BUF;

        uint32_t bh[8][4], bl[8][4];
#pragma unroll
        for (int j = 0; j < 8; j++) {
            uint32_t ba = bb + (uint32_t)(wn * 64 + j * 8 + brow) * XA_ROWB + bquad16;
            ldsm_x4(bh[j], ba);
            ldsm_x4(bl[j], ba + XA_HL);
        }
#pragma unroll
        for (int sh = 0; sh < 2; sh++) {
            uint32_t ah[2][4], al[2][4];
#pragma unroll
            for (int i = 0; i < 2; i++) {
                uint32_t aa = ab + (uint32_t)(wm * 32 + i * 16 + arow) * XA_ROWB +
                              sh * 32 + acol16;
                ldsm_x4(ah[i], aa);
                ldsm_x4(al[i], aa + XA_HL);
            }
#pragma unroll
            for (int i = 0; i < 2; i++)
#pragma unroll
                for (int j = 0; j < 8; j++) {
                    mma_bf16(acc[i][j], ah[i], bh[j][sh * 2], bh[j][sh * 2 + 1]);
                    mma_bf16(acc[i][j], ah[i], bl[j][sh * 2], bl[j][sh * 2 + 1]);
                    mma_bf16(acc[i][j], al[i], bh[j][sh * 2], bh[j][sh * 2 + 1]);
                }
        }
        __syncthreads();
    }

    const int qrow = lane >> 2;
    const int qcol = (lane & 3) * 2;
#pragma unroll
    for (int i = 0; i < 2; i++) {
        int m0 = brow0 + wm * 32 + i * 16 + qrow;
#pragma unroll
        for (int j = 0; j < 8; j++) {
            int n0 = bcol0 + wn * 64 + j * 8 + qcol;
            float bi0 = bias[n0], bi1 = bias[n0 + 1];
            float v00 = acc[i][j][0] + bi0, v01 = acc[i][j][1] + bi1;
            float v10 = acc[i][j][2] + bi0, v11 = acc[i][j][3] + bi1;
            if (EPI == 1) {
                v00 = tanhf(v00); v01 = tanhf(v01);
                v10 = tanhf(v10); v11 = tanhf(v11);
            }
            *(float2*)(C + (size_t)m0 * ND + n0) = make_float2(v00, v01);
            *(float2*)(C + (size_t)(m0 + 8) * ND + n0) = make_float2(v10, v11);
        }
    }
}

// ---------------- grid-wide barrier (R15-proven nanosleep backoff) ------------
__device__ __forceinline__ void grid_bar() {
    __syncthreads();
    if (threadIdx.x == 0) {
        __threadfence();
        unsigned int arr = atomicAdd(&g_barrier, 1u);
        unsigned int target = arr - (arr % NBLK) + NBLK;
        while (*(volatile unsigned int*)&g_barrier < target) __nanosleep(20);
    }
    __syncthreads();
}

// ---------------- persistent HMMA recurrence ----------------------------------
// 96 blocks x 256 threads. A chunks: ONE 32KB cp.async.bulk each (hi|lo packed),
// 2-buffer pipeline; W hi/lo resident in smem. (R15 structure + unified bulk.)
__global__ void __launch_bounds__(NTHR, 1)
recurrence_kernel(const float* __restrict__ W_hh, const float* __restrict__ b_hh) {
    extern __shared__ char smem[];
    const uint32_t sb = smem_u32(smem);
    const int tid = threadIdx.x;
    const int wid = tid >> 5;
    const int lane = tid & 31;
    const int blk = blockIdx.x;
    const int col0 = blk * NWCOL;
    const int wm = wid & 3;
    const int wn = wid >> 2;

    if (tid == 0) {
        mbar_init(sb + SM_MBAR, 1);
        mbar_init(sb + SM_MBAR + 8, 1);
    }

    // W slice: fp32 -> bf16 hi/lo, padded row-major (n,k), smem-resident
    for (int idx = tid; idx < NWCOL * HH; idx += NTHR) {
        int r = idx >> 10;
        int k = idx & 1023;
        float w = W_hh[(size_t)(col0 + r) * HH + k];
        __nv_bfloat16 hi = __float2bfloat16(w);
        __nv_bfloat16 lo = __float2bfloat16(w - __bfloat162float(hi));
        *(__nv_bfloat16*)(smem + SM_W + r * W_ROWB + k * 2) = hi;
        *(__nv_bfloat16*)(smem + SM_W + W_HL + r * W_ROWB + k * 2) = lo;
    }
    __syncthreads();

    // A-fragment lane constants: row r = wm*32 + i*16 + arow; SW128 layout
    const int arow = (lane & 7) + ((lane >> 3) & 1) * 8;
    const uint32_t acol16 = (uint32_t)(lane >> 4) * 16;   // BYTES
    uint32_t rbase[2], rxor[2];
#pragma unroll
    for (int i = 0; i < 2; i++) {
        int r = wm * 32 + i * 16 + arow;
        rbase[i] = ((uint32_t)(r >> 3) << 10) + ((uint32_t)(r & 7) << 7);
        rxor[i] = (uint32_t)(r & 7) << 4;
    }
    // B-fragment x4 lane mapping
    const int brow4 = wn * 16 + ((lane >> 4) & 1) * 8 + (lane & 7);
    const int bcol4 = ((lane >> 3) & 1) * 8;
    const uint32_t wb_hi = sb + SM_W + (uint32_t)brow4 * W_ROWB + (uint32_t)bcol4 * 2;
    const uint32_t wb_lo = wb_hi + W_HL;

    const char* sstream = (const char*)g_s;

    // phase-B loop invariants: h4 = 4*tid
    const int h4 = (tid & 255) << 2;
    const float4 bz  = *(const float4*)(b_hh + h4);
    const float4 brr = *(const float4*)(b_hh + HH + h4);
    const float4 bnn = *(const float4*)(b_hh + 2 * HH + h4);

    uint32_t parity[2] = {0u, 0u};

    for (int t = 0; t < TT; t++) {
        float a0[2][2][4], a1[2][2][4], a2[2][2][4];
#pragma unroll
        for (int i = 0; i < 2; i++)
#pragma unroll
            for (int j = 0; j < 2; j++)
#pragma unroll
                for (int q = 0; q < 4; q++) {
                    a0[i][j][q] = 0.0f; a1[i][j][q] = 0.0f; a2[i][j][q] = 0.0f;
                }

        if (t > 0) {
            const size_t tbase = (size_t)(t - 1) * NCHUNK * A_BUF;
            // prefetch chunk 0 into buf 0 (ONE 32KB bulk)
            if (tid == 0) {
                uint32_t mb = sb + SM_MBAR;
                mbar_expect_tx(mb, A_BUF);
                bulk_cp(sb + SM_A, sstream + tbase, A_BUF, mb);
            }

            for (int c = 0; c < NCHUNK; c++) {
                int buf = c & 1;
                if (c + 1 < NCHUNK && tid == 0) {
                    int nbuf = buf ^ 1;
                    uint32_t mb = sb + SM_MBAR + nbuf * 8;
                    mbar_expect_tx(mb, A_BUF);
                    bulk_cp(sb + SM_A + nbuf * A_BUF,
                            sstream + tbase + (size_t)(c + 1) * A_BUF, A_BUF, mb);
                }
                mbar_wait(sb + SM_MBAR + buf * 8, parity[buf]);
                parity[buf] ^= 1;

                uint32_t abuf = sb + SM_A + buf * A_BUF;
#pragma unroll
                for (int s = 0; s < 4; s++) {
                    uint32_t bytecol = (uint32_t)s * 32 + acol16;
                    uint32_t kgb = (uint32_t)(c * KC + s * 16) * 2;
                    uint32_t ah[2][4], al[2][4];
#pragma unroll
                    for (int i = 0; i < 2; i++) {
                        uint32_t aoff = rbase[i] + (bytecol ^ rxor[i]);
                        ldsm_x4(ah[i], abuf + aoff);
                        ldsm_x4(al[i], abuf + A_HL + aoff);
                    }
                    uint32_t bh[4], bl[4];
                    ldsm_x4(bh, wb_hi + kgb);
                    ldsm_x4(bl, wb_lo + kgb);
#pragma unroll
                    for (int i = 0; i < 2; i++) {
                        mma_bf16(a0[i][0], ah[i], bh[0], bh[1]);
                        mma_bf16(a0[i][1], ah[i], bh[2], bh[3]);
                    }
#pragma unroll
                    for (int i = 0; i < 2; i++) {
                        mma_bf16(a1[i][0], ah[i], bl[0], bl[1]);
                        mma_bf16(a1[i][1], ah[i], bl[2], bl[3]);
                    }
#pragma unroll
                    for (int i = 0; i < 2; i++) {
                        mma_bf16(a2[i][0], al[i], bh[0], bh[1]);
                        mma_bf16(a2[i][1], al[i], bh[2], bh[3]);
                    }
                }
                __syncthreads();   // all warps done reading buf before refill
            }
        }

        // epilogue: combine terms -> g_hg
        {
            int qrow = lane >> 2;
            int qcol = (lane & 3) * 2;
#pragma unroll
            for (int i = 0; i < 2; i++) {
                int m0 = wm * 32 + i * 16 + qrow;
#pragma unroll
                for (int j = 0; j < 2; j++) {
                    int n0 = col0 + wn * 16 + j * 8 + qcol;
                    float v0 = a0[i][j][0] + a1[i][j][0] + a2[i][j][0];
                    float v1 = a0[i][j][1] + a1[i][j][1] + a2[i][j][1];
                    float v2 = a0[i][j][2] + a1[i][j][2] + a2[i][j][2];
                    float v3 = a0[i][j][3] + a1[i][j][3] + a2[i][j][3];
                    *(float2*)(g_hg + (size_t)m0 * G3 + n0) = make_float2(v0, v1);
                    *(float2*)(g_hg + (size_t)(m0 + 8) * G3 + n0) = make_float2(v2, v3);
                }
            }
        }

        grid_bar();  // hg complete everywhere

        // ---- phase B: gates + fractional memory, float4-vectorized ----------
        const int ng = (BB * HH) / 4;
        for (int g = blk * NTHR + tid; g < ng; g += NBLK * NTHR) {
            int b = g >> 8;
            int hc = g & 255;
            const float4* xrow = (const float4*)(g_xg + ((size_t)b * TT + t) * G3);
            float4 xz = xrow[hc];
            float4 xr = xrow[256 + hc];
            float4 xn = xrow[512 + hc];
            const float4* hrow = (const float4*)(g_hg + (size_t)b * G3);
            float4 hz4 = __ldcg(hrow + hc);
            float4 hr4 = __ldcg(hrow + 256 + hc);
            float4 hn4 = __ldcg(hrow + 512 + hc);

            float m0 = 0.f, m1 = 0.f, m2 = 0.f, m3 = 0.f;
#pragma unroll
            for (int k = 0; k < KK; k++) {
                int s = (t + k) & (KK - 1);
                float4 wv = *(const float4*)(g_w + (size_t)k * HH + h4);
                float4 rv = __ldcg((const float4*)(g_ring +
                                   ((size_t)s * BB + b) * HH + h4));
                m0 += wv.x * rv.x; m1 += wv.y * rv.y;
                m2 += wv.z * rv.z; m3 += wv.w * rv.w;
            }

            float XZ[4] = {xz.x, xz.y, xz.z, xz.w};
            float XR[4] = {xr.x, xr.y, xr.z, xr.w};
            float XN[4] = {xn.x, xn.y, xn.z, xn.w};
            float HZ[4] = {hz4.x + bz.x, hz4.y + bz.y, hz4.z + bz.z, hz4.w + bz.w};
            float HR[4] = {hr4.x + brr.x, hr4.y + brr.y, hr4.z + brr.z, hr4.w + brr.w};
            float HN[4] = {hn4.x + bnn.x, hn4.y + bnn.y, hn4.z + bnn.z, hn4.w + bnn.w};
            float MM[4] = {m0, m1, m2, m3};
            float hnew[4];
#pragma unroll
            for (int q = 0; q < 4; q++) {
                float z = 1.0f / (1.0f + expf(-(XZ[q] + HZ[q])));
                float r = 1.0f / (1.0f + expf(-(XR[q] + HR[q])));
                float n = tanhf(XN[q] + r * HN[q]);
                hnew[q] = z * n - MM[q];
            }

            *(float4*)(g_ring + ((size_t)(t & (KK - 1)) * BB + b) * HH + h4) =
                make_float4(hnew[0], hnew[1], hnew[2], hnew[3]);

            __nv_bfloat16 hb[4], lb[4];
#pragma unroll
            for (int q = 0; q < 4; q++) {
                hb[q] = __float2bfloat16(hnew[q]);
                lb[q] = __float2bfloat16(hnew[q] - __bfloat162float(hb[q]));
            }
            uint2 hpack, lpack;
            hpack.x = ((uint32_t)*(unsigned short*)&hb[1] << 16) | *(unsigned short*)&hb[0];
            hpack.y = ((uint32_t)*(unsigned short*)&hb[3] << 16) | *(unsigned short*)&hb[2];
            lpack.x = ((uint32_t)*(unsigned short*)&lb[1] << 16) | *(unsigned short*)&lb[0];
            lpack.y = ((uint32_t)*(unsigned short*)&lb[3] << 16) | *(unsigned short*)&lb[2];

            // linear copy (decode)
            size_t hidx = ((size_t)b * TT + t) * HH + h4;
            *(uint2*)(g_hallhi + hidx) = hpack;
            *(uint2*)(g_halllo + hidx) = lpack;

            // pre-swizzled unified stream: [t][chunk][hi 16K | lo 16K]
            int cch = h4 >> 6;
            uint32_t within = ((uint32_t)(b & 7) << 7) +
                              ((((uint32_t)(h4 & 63)) << 1) ^ (((uint32_t)(b & 7)) << 4));
            size_t soff = ((size_t)t * NCHUNK + cch) * A_BUF +
                          ((size_t)(b >> 3) << 10) + within;
            *(uint2*)((char*)g_s + soff) = hpack;
            *(uint2*)((char*)g_s + soff + A_HL) = lpack;
        }

        grid_bar();  // h_new visible everywhere before next step's A stream
    }
}

// ---------------- launch ------------------------------------------------------
extern "C" void kernel_launch(void* const* d_in, const int* in_sizes, int n_in,
                              void* d_out, int out_size) {
    const float* input_seq = (const float*)d_in[0];
    const float* mem_para  = (const float*)d_in[1];
    const float* W_ih      = (const float*)d_in[2];
    const float* W_hh      = (const float*)d_in[3];
    const float* b_ih      = (const float*)d_in[4];
    const float* b_hh      = (const float*)d_in[5];
    const float* W_out     = (const float*)d_in[6];
    const float* b_out     = (const float*)d_in[7];
    float* out = (float*)d_out;

    cudaFuncSetAttribute(recurrence_kernel,
                         cudaFuncAttributeMaxDynamicSharedMemorySize, SMEM_REC);
    cudaFuncSetAttribute(gemm_hmma<II, G3, 0>,
                         cudaFuncAttributeMaxDynamicSharedMemorySize, XSMEM);
    cudaFuncSetAttribute(gemm_hmma<HH, OO, 1>,
                         cudaFuncAttributeMaxDynamicSharedMemorySize, XSMEM);

    float *xg, *ring;
    __nv_bfloat16 *xhi, *xlo, *wihhi, *wihlo, *hallhi, *halllo, *wohi, *wolo;
    cudaGetSymbolAddress((void**)&xg, g_xg);
    cudaGetSymbolAddress((void**)&ring, g_ring);
    cudaGetSymbolAddress((void**)&xhi, g_xhi);
    cudaGetSymbolAddress((void**)&xlo, g_xlo);
    cudaGetSymbolAddress((void**)&wihhi, g_wihhi);
    cudaGetSymbolAddress((void**)&wihlo, g_wihlo);
    cudaGetSymbolAddress((void**)&hallhi, g_hallhi);
    cudaGetSymbolAddress((void**)&halllo, g_halllo);
    cudaGetSymbolAddress((void**)&wohi, g_wohi);
    cudaGetSymbolAddress((void**)&wolo, g_wolo);

    compute_w_kernel<<<1, 1024>>>(mem_para);
    init_kernel<<<1024, 256>>>();
    convert_kernel<<<2048, 256>>>(input_seq, W_ih, W_out);

    {   // xg = input_seq @ W_ih^T + b_ih  (HMMA 3-term bf16)
        dim3 grid(G3 / 128, (BB * TT) / 128);
        gemm_hmma<II, G3, 0><<<grid, 256, XSMEM>>>(xhi, xlo, wihhi, wihlo, xg, b_ih);
    }

    recurrence_kernel<<<NBLK, NTHR, SMEM_REC>>>(W_hh, b_hh);

    {   // decode: out[b*TT+t][o] = tanh(Hall @ W_out^T + b_out)  (HMMA)
        dim3 grid(OO / 128, (BB * TT) / 128);
        gemm_hmma<HH, OO, 1><<<grid, 256, XSMEM>>>(hallhi, halllo, wohi, wolo, out, b_out);
    }

    size_t dec_elems = (size_t)BB * TT * OO;
    size_t hbuf_elems = (size_t)KK * BB * HH;
    if ((size_t)out_size >= dec_elems + hbuf_elems) {
        copy_kernel<<<1024, 256>>>(ring, out + dec_elems, hbuf_elems);
    }
}